// round 1
// baseline (speedup 1.0000x reference)
#include <cuda_runtime.h>
#include <cuda_bf16.h>
#include <stdint.h>

typedef __nv_bfloat16 bf16;

#define S_LEN 512
#define BATCH 128
#define IDIM  1024
#define HDIM  1024
#define KDIM  2048       // x (1024) ++ h (1024)
#define N3    3072       // 3 gates * H, interleaved col = 3*j + gate
#define TN    48         // cols per block -> 16 j's, all 3 gates
#define KT    32         // K tile
#define ASTR  40         // smem row stride (bf16) : conflict-free + 16B aligned

// ---------------- device scratch (no allocations allowed) ----------------
__device__ bf16  g_x_hi[S_LEN*BATCH*IDIM];
__device__ bf16  g_x_lo[S_LEN*BATCH*IDIM];
__device__ bf16  g_W_hi[2*N3*KDIM];          // [dir][n][k], n interleaved
__device__ bf16  g_W_lo[2*N3*KDIM];
__device__ float g_bias[2][4][HDIM];         // br, bz, bin, bhn
__device__ float g_h[2*BATCH*HDIM];          // fp32 recurrent state [dir][b][j]
__device__ bf16  g_hbf_hi[2*2*BATCH*HDIM];   // [parity][dir][b][j]
__device__ bf16  g_hbf_lo[2*2*BATCH*HDIM];

// ---------------- helpers ----------------
__device__ __forceinline__ void split2(float v, bf16& hi, bf16& lo) {
    hi = __float2bfloat16(v);
    lo = __float2bfloat16(v - __bfloat162float(hi));
}

__device__ __forceinline__ void cp16(bf16* dst, const bf16* src) {
    unsigned d = (unsigned)__cvta_generic_to_shared(dst);
    asm volatile("cp.async.cg.shared.global [%0], [%1], 16;\n" :: "r"(d), "l"(src));
}

__device__ __forceinline__ void mma16816(float c[4], const uint32_t a[4],
                                         uint32_t b0, uint32_t b1) {
    asm volatile(
        "mma.sync.aligned.m16n8k16.row.col.f32.bf16.bf16.f32 "
        "{%0,%1,%2,%3},{%4,%5,%6,%7},{%8,%9},{%0,%1,%2,%3};"
        : "+f"(c[0]), "+f"(c[1]), "+f"(c[2]), "+f"(c[3])
        : "r"(a[0]), "r"(a[1]), "r"(a[2]), "r"(a[3]), "r"(b0), "r"(b1));
}

// ---------------- prep kernels ----------------
__global__ void pack_x_kernel(const float* __restrict__ x) {
    int i = blockIdx.x * 256 + threadIdx.x;   // grid exactly covers S*B*I
    bf16 hi, lo;
    split2(x[i], hi, lo);
    g_x_hi[i] = hi;
    g_x_lo[i] = lo;
}

__global__ void pack_w_kernel(const float* __restrict__ Wih_f, const float* __restrict__ Whh_f,
                              const float* __restrict__ Wih_b, const float* __restrict__ Whh_b) {
    int idx = blockIdx.x * 256 + threadIdx.x;  // over 2*N3*KDIM
    int k   = idx % KDIM;
    int n   = (idx / KDIM) % N3;
    int dir = idx / (KDIM * N3);
    int j = n / 3, g = n % 3;
    int srow = g * HDIM + j;
    const float* Wih = dir ? Wih_b : Wih_f;
    const float* Whh = dir ? Whh_b : Whh_f;
    float v = (k < IDIM) ? Wih[srow * IDIM + k] : Whh[srow * HDIM + (k - IDIM)];
    bf16 hi, lo;
    split2(v, hi, lo);
    g_W_hi[idx] = hi;
    g_W_lo[idx] = lo;
}

__global__ void pack_bias_kernel(const float* __restrict__ bih_f, const float* __restrict__ bhh_f,
                                 const float* __restrict__ bih_b, const float* __restrict__ bhh_b) {
    int i = blockIdx.x * 256 + threadIdx.x;   // 0..2047
    int dir = i >> 10, j = i & 1023;
    const float* bih = dir ? bih_b : bih_f;
    const float* bhh = dir ? bhh_b : bhh_f;
    g_bias[dir][0][j] = bih[j] + bhh[j];                 // r
    g_bias[dir][1][j] = bih[HDIM + j] + bhh[HDIM + j];   // z
    g_bias[dir][2][j] = bih[2 * HDIM + j];               // n (input part)
    g_bias[dir][3][j] = bhh[2 * HDIM + j];               // n (hidden part)
}

__global__ void init_h_kernel() {
    int i = blockIdx.x * 256 + threadIdx.x;   // over 2*2*B*H = 524288
    if (i < 2 * BATCH * HDIM) g_h[i] = 0.f;
    bf16 z = __float2bfloat16(0.f);
    g_hbf_hi[i] = z;
    g_hbf_lo[i] = z;
}

// ---------------- recurrent step kernel ----------------
// Grid: (N3/TN = 64, 2 dirs). Block: 256 threads (8 warps).
// Block computes C[128, TN] = [x_t ; h] @ Wpack^T with split accumulators
// per K-half (gi vs gh), then the GRU gate epilogue for its 16 j's.
__global__ void __launch_bounds__(256) gru_step(float* __restrict__ out, int step) {
    extern __shared__ char smraw[];
    bf16* sm = (bf16*)smraw;

    const int dir  = blockIdx.y;
    const int nblk = blockIdx.x;
    const int t    = threadIdx.x;
    const int warp = t >> 5, lane = t & 31;
    const int grp  = lane >> 2, tq = lane & 3;
    const int rpar = step & 1;                    // read parity for h bf buffers
    const int s_x  = dir ? (S_LEN - 1 - step) : step;

    // smem regions (bf16 index):
    //   A[buf][half] : 128 x ASTR     (4 * 5120 bf16)
    //   B[buf][half] : TN  x ASTR     (4 * 1920 bf16)
    auto smA = [&](int buf, int half) { return sm + (buf * 2 + half) * 128 * ASTR; };
    auto smB = [&](int buf, int half) { return sm + 4 * 128 * ASTR + (buf * 2 + half) * TN * ASTR; };

    auto copy_tile = [&](int kt, int buf) {
        const int k0 = kt * KT;
#pragma unroll
        for (int i = 0; i < 2; i++) {
            int idx = t + i * 256;
            int row = idx >> 2;
            int kq  = (idx & 3) * 8;
            int kg  = k0 + kq;
            const bf16 *sh, *sl;
            if (kg < IDIM) {
                int off = (s_x * BATCH + row) * IDIM + kg;
                sh = g_x_hi + off; sl = g_x_lo + off;
            } else {
                int off = ((rpar * 2 + dir) * BATCH + row) * HDIM + (kg - IDIM);
                sh = g_hbf_hi + off; sl = g_hbf_lo + off;
            }
            cp16(smA(buf, 0) + row * ASTR + kq, sh);
            cp16(smA(buf, 1) + row * ASTR + kq, sl);
        }
        if (t < 4 * TN) {
            int nloc = t >> 2;
            int kq   = (t & 3) * 8;
            int off  = (dir * N3 + nblk * TN + nloc) * KDIM + k0 + kq;
            cp16(smB(buf, 0) + nloc * ASTR + kq, g_W_hi + off);
            cp16(smB(buf, 1) + nloc * ASTR + kq, g_W_lo + off);
        }
    };

    float acc0[6][4], acc1[6][4];   // K-half 0 (gi) and K-half 1 (gh)
#pragma unroll
    for (int i = 0; i < 6; i++)
#pragma unroll
        for (int q = 0; q < 4; q++) { acc0[i][q] = 0.f; acc1[i][q] = 0.f; }

    copy_tile(0, 0);
    asm volatile("cp.async.commit_group;");

    const int NKT = KDIM / KT;   // 64
    int cur = 0;
    for (int kt = 0; kt < NKT; ++kt) {
        if (kt + 1 < NKT) {
            copy_tile(kt + 1, cur ^ 1);
            asm volatile("cp.async.commit_group;");
            asm volatile("cp.async.wait_group 1;");
        } else {
            asm volatile("cp.async.wait_group 0;");
        }
        __syncthreads();

        const bf16* pAh = smA(cur, 0);
        const bf16* pAl = smA(cur, 1);
        const bf16* pBh = smB(cur, 0);
        const bf16* pBl = smB(cur, 1);

        auto do_half = [&](float (&acc)[6][4]) {
#pragma unroll
            for (int ks = 0; ks < 2; ++ks) {
                const int kb = ks * 16 + tq * 2;
                const int r0 = warp * 16 + grp;
                uint32_t ah[4], al[4];
                ah[0] = *(const uint32_t*)(pAh + r0 * ASTR + kb);
                ah[1] = *(const uint32_t*)(pAh + (r0 + 8) * ASTR + kb);
                ah[2] = *(const uint32_t*)(pAh + r0 * ASTR + kb + 8);
                ah[3] = *(const uint32_t*)(pAh + (r0 + 8) * ASTR + kb + 8);
                al[0] = *(const uint32_t*)(pAl + r0 * ASTR + kb);
                al[1] = *(const uint32_t*)(pAl + (r0 + 8) * ASTR + kb);
                al[2] = *(const uint32_t*)(pAl + r0 * ASTR + kb + 8);
                al[3] = *(const uint32_t*)(pAl + (r0 + 8) * ASTR + kb + 8);
#pragma unroll
                for (int nt = 0; nt < 6; ++nt) {
                    const int nb = nt * 8 + grp;
                    uint32_t bh0 = *(const uint32_t*)(pBh + nb * ASTR + kb);
                    uint32_t bh1 = *(const uint32_t*)(pBh + nb * ASTR + kb + 8);
                    uint32_t bl0 = *(const uint32_t*)(pBl + nb * ASTR + kb);
                    uint32_t bl1 = *(const uint32_t*)(pBl + nb * ASTR + kb + 8);
                    mma16816(acc[nt], ah, bh0, bh1);   // hi*hi
                    mma16816(acc[nt], ah, bl0, bl1);   // hi*lo
                    mma16816(acc[nt], al, bh0, bh1);   // lo*hi
                }
            }
        };
        if (kt < NKT / 2) do_half(acc0); else do_half(acc1);

        __syncthreads();
        cur ^= 1;
    }

    // ---- epilogue: dump accumulators to smem, then gate math ----
    float* sC = (float*)smraw;   // [2][128][49]
    {
        const int row  = warp * 16 + grp;
        const int colb = tq * 2;
#pragma unroll
        for (int nt = 0; nt < 6; ++nt) {
            int col = nt * 8 + colb;
            sC[(0 * 128 + row) * 49 + col]         = acc0[nt][0];
            sC[(0 * 128 + row) * 49 + col + 1]     = acc0[nt][1];
            sC[(0 * 128 + row + 8) * 49 + col]     = acc0[nt][2];
            sC[(0 * 128 + row + 8) * 49 + col + 1] = acc0[nt][3];
            sC[(1 * 128 + row) * 49 + col]         = acc1[nt][0];
            sC[(1 * 128 + row) * 49 + col + 1]     = acc1[nt][1];
            sC[(1 * 128 + row + 8) * 49 + col]     = acc1[nt][2];
            sC[(1 * 128 + row + 8) * 49 + col + 1] = acc1[nt][3];
        }
    }
    __syncthreads();

    const int wpar = rpar ^ 1;
#pragma unroll
    for (int q = 0; q < 8; q++) {
        int p  = t * 8 + q;          // 2048 (b, j) pairs
        int b  = p >> 4, jj = p & 15;
        int j  = nblk * 16 + jj;
        int c  = jj * 3;             // interleaved: r, z, n
        float gr  = sC[b * 49 + c]       + sC[(128 + b) * 49 + c]       + g_bias[dir][0][j];
        float gz  = sC[b * 49 + c + 1]   + sC[(128 + b) * 49 + c + 1]   + g_bias[dir][1][j];
        float gni = sC[b * 49 + c + 2]   + g_bias[dir][2][j];
        float gnh = sC[(128 + b) * 49 + c + 2] + g_bias[dir][3][j];
        float r = 1.f / (1.f + __expf(-gr));
        float z = 1.f / (1.f + __expf(-gz));
        float n = tanhf(gni + r * gnh);
        int   hidx = (dir * BATCH + b) * HDIM + j;
        float hold = g_h[hidx];
        float hnew = (1.f - z) * n + z * hold;
        g_h[hidx] = hnew;
        bf16 hi, lo;
        split2(hnew, hi, lo);
        int hb = ((wpar * 2 + dir) * BATCH + b) * HDIM + j;
        g_hbf_hi[hb] = hi;
        g_hbf_lo[hb] = lo;
        out[((size_t)step * BATCH + b) * (2 * HDIM) + dir * HDIM + j] = hnew;
    }
}

// ---------------- launch ----------------
extern "C" void kernel_launch(void* const* d_in, const int* in_sizes, int n_in,
                              void* d_out, int out_size) {
    const float* x     = (const float*)d_in[0];
    const float* Wih_f = (const float*)d_in[1];
    const float* Whh_f = (const float*)d_in[2];
    const float* bih_f = (const float*)d_in[3];
    const float* bhh_f = (const float*)d_in[4];
    const float* Wih_b = (const float*)d_in[5];
    const float* Whh_b = (const float*)d_in[6];
    const float* bih_b = (const float*)d_in[7];
    const float* bhh_b = (const float*)d_in[8];
    float* out = (float*)d_out;

    const int SMEM = 4 * 128 * ASTR * 2 + 4 * TN * ASTR * 2;   // 56320 B
    cudaFuncSetAttribute(gru_step, cudaFuncAttributeMaxDynamicSharedMemorySize, SMEM);

    pack_x_kernel<<<S_LEN * BATCH * IDIM / 256, 256>>>(x);
    pack_w_kernel<<<2 * N3 * KDIM / 256, 256>>>(Wih_f, Whh_f, Wih_b, Whh_b);
    pack_bias_kernel<<<8, 256>>>(bih_f, bhh_f, bih_b, bhh_b);
    init_h_kernel<<<2 * 2 * BATCH * HDIM / 256, 256>>>();

    for (int s = 0; s < S_LEN; ++s)
        gru_step<<<dim3(N3 / TN, 2), 256, SMEM>>>(out, s);
}

// round 2
// speedup vs baseline: 1.1752x; 1.1752x over previous
#include <cuda_runtime.h>
#include <cuda_bf16.h>
#include <stdint.h>

typedef __nv_bfloat16 bf16;

#define S_LEN 512
#define BATCH 128
#define IDIM  1024
#define HDIM  1024
#define KDIM  2048       // packed weights: k<1024 -> Wih, k>=1024 -> Whh
#define N3    3072       // 3 gates * H, interleaved col = 3*j + gate
#define TN    48         // cols per block
#define KT    32         // K tile
#define ASTR  40         // smem row stride (bf16): conflict-free, 16B-aligned rows
#define NSTG  3          // pipeline stages
#define MTOT  (S_LEN*BATCH)   // 65536 rows of gi per dir

// ---------------- device scratch ----------------
__device__ bf16  g_x_hi[S_LEN*BATCH*IDIM];
__device__ bf16  g_x_lo[S_LEN*BATCH*IDIM];
__device__ bf16  g_W_hi[2*N3*KDIM];
__device__ bf16  g_W_lo[2*N3*KDIM];
__device__ float g_bias[2][4][HDIM];         // br, bz, b_in, b_hn
__device__ float g_h[2*BATCH*HDIM];          // fp32 recurrent state
__device__ bf16  g_hbf_hi[2*2*BATCH*HDIM];   // [parity][dir][b][j]
__device__ bf16  g_hbf_lo[2*2*BATCH*HDIM];
__device__ float g_gi[2*MTOT*N3];            // precomputed x@Wih^T (interleaved cols), 1.6GB

// ---------------- helpers ----------------
__device__ __forceinline__ void split2(float v, bf16& hi, bf16& lo) {
    hi = __float2bfloat16(v);
    lo = __float2bfloat16(v - __bfloat162float(hi));
}

__device__ __forceinline__ void cp16(bf16* dst, const bf16* src) {
    unsigned d = (unsigned)__cvta_generic_to_shared(dst);
    asm volatile("cp.async.cg.shared.global [%0], [%1], 16;\n" :: "r"(d), "l"(src));
}

__device__ __forceinline__ uint32_t smaddr(const void* p) {
    return (uint32_t)__cvta_generic_to_shared(p);
}

__device__ __forceinline__ void ldsm_x4(uint32_t r[4], uint32_t a) {
    asm volatile("ldmatrix.sync.aligned.m8n8.x4.shared.b16 {%0,%1,%2,%3},[%4];"
                 : "=r"(r[0]), "=r"(r[1]), "=r"(r[2]), "=r"(r[3]) : "r"(a));
}

__device__ __forceinline__ void mma16816(float c[4], const uint32_t a[4],
                                         uint32_t b0, uint32_t b1) {
    asm volatile(
        "mma.sync.aligned.m16n8k16.row.col.f32.bf16.bf16.f32 "
        "{%0,%1,%2,%3},{%4,%5,%6,%7},{%8,%9},{%0,%1,%2,%3};"
        : "+f"(c[0]), "+f"(c[1]), "+f"(c[2]), "+f"(c[3])
        : "r"(a[0]), "r"(a[1]), "r"(a[2]), "r"(a[3]), "r"(b0), "r"(b1));
}

// per-stage smem layout (bf16 units)
#define STAGE_ELEMS (2*128*ASTR + 2*TN*ASTR)     // Ahi, Alo, Bhi, Blo = 14080
#define SMEM_BYTES  (NSTG * STAGE_ELEMS * 2)     // 84480

// ---------------- prep kernels ----------------
__global__ void pack_x_kernel(const float* __restrict__ x) {
    int i = blockIdx.x * 256 + threadIdx.x;
    bf16 hi, lo; split2(x[i], hi, lo);
    g_x_hi[i] = hi; g_x_lo[i] = lo;
}

__global__ void pack_w_kernel(const float* __restrict__ Wih_f, const float* __restrict__ Whh_f,
                              const float* __restrict__ Wih_b, const float* __restrict__ Whh_b) {
    int idx = blockIdx.x * 256 + threadIdx.x;
    int k   = idx % KDIM;
    int n   = (idx / KDIM) % N3;
    int dir = idx / (KDIM * N3);
    int j = n / 3, g = n % 3;
    int srow = g * HDIM + j;
    const float* Wih = dir ? Wih_b : Wih_f;
    const float* Whh = dir ? Whh_b : Whh_f;
    float v = (k < IDIM) ? Wih[srow * IDIM + k] : Whh[srow * HDIM + (k - IDIM)];
    bf16 hi, lo; split2(v, hi, lo);
    g_W_hi[idx] = hi; g_W_lo[idx] = lo;
}

__global__ void pack_bias_kernel(const float* __restrict__ bih_f, const float* __restrict__ bhh_f,
                                 const float* __restrict__ bih_b, const float* __restrict__ bhh_b) {
    int i = blockIdx.x * 256 + threadIdx.x;   // 0..2047
    int dir = i >> 10, j = i & 1023;
    const float* bih = dir ? bih_b : bih_f;
    const float* bhh = dir ? bhh_b : bhh_f;
    g_bias[dir][0][j] = bih[j] + bhh[j];
    g_bias[dir][1][j] = bih[HDIM + j] + bhh[HDIM + j];
    g_bias[dir][2][j] = bih[2 * HDIM + j];
    g_bias[dir][3][j] = bhh[2 * HDIM + j];
}

__global__ void init_h_kernel() {
    int i = blockIdx.x * 256 + threadIdx.x;   // 2*2*B*H
    if (i < 2 * BATCH * HDIM) g_h[i] = 0.f;
    bf16 z = __float2bfloat16(0.f);
    g_hbf_hi[i] = z; g_hbf_lo[i] = z;
}

// ---------------- shared mainloop pieces (macro-free via inline lambdas) ----------------
// Both GEMM kernels: C[128, TN] += A[128, 1024] @ B[TN, 1024]^T with 3-term split.

struct Frag { float acc[6][4]; };

__device__ __forceinline__ void compute_tile(bf16* stage, int warp, int lane, Frag& f) {
    bf16* pAh = stage;
    bf16* pAl = stage + 128 * ASTR;
    bf16* pBh = stage + 2 * 128 * ASTR;
    bf16* pBl = stage + 2 * 128 * ASTR + TN * ASTR;
    const int r0 = warp * 16;
#pragma unroll
    for (int ks = 0; ks < 2; ++ks) {
        const int kb = ks * 16;
        uint32_t ah[4], al[4];
        {
            int row = r0 + (lane & 15);
            int coff = (lane >> 4) * 8;
            ldsm_x4(ah, smaddr(pAh + row * ASTR + kb + coff));
            ldsm_x4(al, smaddr(pAl + row * ASTR + kb + coff));
        }
#pragma unroll
        for (int nt = 0; nt < 6; ++nt) {
            uint32_t b4[4];
            const bf16* bbase = (lane < 16) ? pBh : pBl;
            int brow = nt * 8 + (lane & 7);
            int bcol = kb + ((lane >> 3) & 1) * 8;
            ldsm_x4(b4, smaddr(bbase + brow * ASTR + bcol));
            mma16816(f.acc[nt], ah, b4[0], b4[1]);   // hi*hi
            mma16816(f.acc[nt], ah, b4[2], b4[3]);   // hi*lo
            mma16816(f.acc[nt], al, b4[0], b4[1]);   // lo*hi
        }
    }
}

// ---------------- pre-GEMM: gi = x @ Wih^T for all steps ----------------
// grid: (MTOT/128, N3/TN, 2), block 256
__global__ void __launch_bounds__(256) gi_gemm(int unused) {
    extern __shared__ char smraw[];
    bf16* sm = (bf16*)smraw;

    const int mblk = blockIdx.x, nblk = blockIdx.y, dir = blockIdx.z;
    const int t = threadIdx.x, warp = t >> 5, lane = t & 31;
    const int grp = lane >> 2, tq = lane & 3;

    auto stage = [&](int s) { return sm + s * STAGE_ELEMS; };

    auto copy_tile = [&](int kt, int buf) {
        bf16* st = stage(buf);
        const int k0 = kt * KT;
#pragma unroll
        for (int i = 0; i < 2; i++) {
            int idx = t + i * 256;
            int row = idx >> 2;
            int kq  = (idx & 3) * 8;
            int off = (mblk * 128 + row) * IDIM + k0 + kq;
            cp16(st + row * ASTR + kq, g_x_hi + off);
            cp16(st + 128 * ASTR + row * ASTR + kq, g_x_lo + off);
        }
        if (t < 4 * TN) {
            int nloc = t >> 2;
            int kq   = (t & 3) * 8;
            int off  = (dir * N3 + nblk * TN + nloc) * KDIM + k0 + kq;
            cp16(st + 2 * 128 * ASTR + nloc * ASTR + kq, g_W_hi + off);
            cp16(st + 2 * 128 * ASTR + TN * ASTR + nloc * ASTR + kq, g_W_lo + off);
        }
    };

    Frag f;
#pragma unroll
    for (int i = 0; i < 6; i++)
#pragma unroll
        for (int q = 0; q < 4; q++) f.acc[i][q] = 0.f;

    copy_tile(0, 0); asm volatile("cp.async.commit_group;");
    copy_tile(1, 1); asm volatile("cp.async.commit_group;");

    const int NKT = IDIM / KT;   // 32
#pragma unroll 1
    for (int kt = 0; kt < NKT; ++kt) {
        if (kt < NKT - 1) asm volatile("cp.async.wait_group 1;");
        else              asm volatile("cp.async.wait_group 0;");
        __syncthreads();
        if (kt + 2 < NKT) { copy_tile(kt + 2, (kt + 2) % NSTG); asm volatile("cp.async.commit_group;"); }
        compute_tile(stage(kt % NSTG), warp, lane, f);
    }

    // epilogue: write fragments straight to g_gi
    const size_t base = ((size_t)dir * MTOT + mblk * 128) * N3 + nblk * TN;
    const int row = warp * 16 + grp;
#pragma unroll
    for (int nt = 0; nt < 6; ++nt) {
        int col = nt * 8 + tq * 2;
        g_gi[base + (size_t)row * N3 + col]           = f.acc[nt][0];
        g_gi[base + (size_t)row * N3 + col + 1]       = f.acc[nt][1];
        g_gi[base + (size_t)(row + 8) * N3 + col]     = f.acc[nt][2];
        g_gi[base + (size_t)(row + 8) * N3 + col + 1] = f.acc[nt][3];
    }
}

// ---------------- recurrent step: gh = h @ Whh^T, then gates ----------------
// grid: (N3/TN = 64, 2 dirs), block 256
__global__ void __launch_bounds__(256) gru_step(float* __restrict__ out, int step) {
    extern __shared__ char smraw[];
    bf16* sm = (bf16*)smraw;

    const int dir  = blockIdx.y;
    const int nblk = blockIdx.x;
    const int t    = threadIdx.x, warp = t >> 5, lane = t & 31;
    const int grp  = lane >> 2, tq = lane & 3;
    const int rpar = step & 1;
    const int s_x  = dir ? (S_LEN - 1 - step) : step;

    auto stage = [&](int s) { return sm + s * STAGE_ELEMS; };

    auto copy_tile = [&](int kt, int buf) {
        bf16* st = stage(buf);
        const int k0 = kt * KT;
#pragma unroll
        for (int i = 0; i < 2; i++) {
            int idx = t + i * 256;
            int row = idx >> 2;
            int kq  = (idx & 3) * 8;
            int off = ((rpar * 2 + dir) * BATCH + row) * HDIM + k0 + kq;
            cp16(st + row * ASTR + kq, g_hbf_hi + off);
            cp16(st + 128 * ASTR + row * ASTR + kq, g_hbf_lo + off);
        }
        if (t < 4 * TN) {
            int nloc = t >> 2;
            int kq   = (t & 3) * 8;
            int off  = (dir * N3 + nblk * TN + nloc) * KDIM + IDIM + k0 + kq;
            cp16(st + 2 * 128 * ASTR + nloc * ASTR + kq, g_W_hi + off);
            cp16(st + 2 * 128 * ASTR + TN * ASTR + nloc * ASTR + kq, g_W_lo + off);
        }
    };

    Frag f;
#pragma unroll
    for (int i = 0; i < 6; i++)
#pragma unroll
        for (int q = 0; q < 4; q++) f.acc[i][q] = 0.f;

    copy_tile(0, 0); asm volatile("cp.async.commit_group;");
    copy_tile(1, 1); asm volatile("cp.async.commit_group;");

    const int NKT = HDIM / KT;   // 32
#pragma unroll 1
    for (int kt = 0; kt < NKT; ++kt) {
        if (kt < NKT - 1) asm volatile("cp.async.wait_group 1;");
        else              asm volatile("cp.async.wait_group 0;");
        __syncthreads();
        if (kt + 2 < NKT) { copy_tile(kt + 2, (kt + 2) % NSTG); asm volatile("cp.async.commit_group;"); }
        compute_tile(stage(kt % NSTG), warp, lane, f);
    }

    // ---- epilogue: accumulators -> smem, then GRU gates ----
    __syncthreads();
    float* sC = (float*)smraw;   // [128][49]
    {
        const int row  = warp * 16 + grp;
        const int colb = tq * 2;
#pragma unroll
        for (int nt = 0; nt < 6; ++nt) {
            int col = nt * 8 + colb;
            sC[row * 49 + col]           = f.acc[nt][0];
            sC[row * 49 + col + 1]       = f.acc[nt][1];
            sC[(row + 8) * 49 + col]     = f.acc[nt][2];
            sC[(row + 8) * 49 + col + 1] = f.acc[nt][3];
        }
    }
    __syncthreads();

    const int wpar = rpar ^ 1;
    const size_t gibase = ((size_t)dir * MTOT + (size_t)s_x * BATCH) * N3 + nblk * TN;
#pragma unroll
    for (int q = 0; q < 8; q++) {
        int p  = t * 8 + q;          // 2048 (b, jj) pairs
        int b  = p >> 4, jj = p & 15;
        int j  = nblk * 16 + jj;
        int c  = jj * 3;
        float ghr = sC[b * 49 + c];
        float ghz = sC[b * 49 + c + 1];
        float gnh = sC[b * 49 + c + 2] + g_bias[dir][3][j];
        const float* gip = g_gi + gibase + (size_t)b * N3 + c;
        float gr  = ghr + gip[0] + g_bias[dir][0][j];
        float gz  = ghz + gip[1] + g_bias[dir][1][j];
        float gni = gip[2] + g_bias[dir][2][j];
        float r = 1.f / (1.f + __expf(-gr));
        float z = 1.f / (1.f + __expf(-gz));
        float n = tanhf(gni + r * gnh);
        int   hidx = (dir * BATCH + b) * HDIM + j;
        float hold = g_h[hidx];
        float hnew = (1.f - z) * n + z * hold;
        g_h[hidx] = hnew;
        bf16 hi, lo; split2(hnew, hi, lo);
        int hb = ((wpar * 2 + dir) * BATCH + b) * HDIM + j;
        g_hbf_hi[hb] = hi;
        g_hbf_lo[hb] = lo;
        out[((size_t)step * BATCH + b) * (2 * HDIM) + dir * HDIM + j] = hnew;
    }
}

// ---------------- launch ----------------
extern "C" void kernel_launch(void* const* d_in, const int* in_sizes, int n_in,
                              void* d_out, int out_size) {
    const float* x     = (const float*)d_in[0];
    const float* Wih_f = (const float*)d_in[1];
    const float* Whh_f = (const float*)d_in[2];
    const float* bih_f = (const float*)d_in[3];
    const float* bhh_f = (const float*)d_in[4];
    const float* Wih_b = (const float*)d_in[5];
    const float* Whh_b = (const float*)d_in[6];
    const float* bih_b = (const float*)d_in[7];
    const float* bhh_b = (const float*)d_in[8];
    float* out = (float*)d_out;

    cudaFuncSetAttribute(gi_gemm,  cudaFuncAttributeMaxDynamicSharedMemorySize, SMEM_BYTES);
    cudaFuncSetAttribute(gru_step, cudaFuncAttributeMaxDynamicSharedMemorySize, SMEM_BYTES);

    pack_x_kernel<<<S_LEN * BATCH * IDIM / 256, 256>>>(x);
    pack_w_kernel<<<2 * N3 * KDIM / 256, 256>>>(Wih_f, Whh_f, Wih_b, Whh_b);
    pack_bias_kernel<<<8, 256>>>(bih_f, bhh_f, bih_b, bhh_b);
    init_h_kernel<<<2 * 2 * BATCH * HDIM / 256, 256>>>();

    gi_gemm<<<dim3(MTOT / 128, N3 / TN, 2), 256, SMEM_BYTES>>>(0);

    for (int s = 0; s < S_LEN; ++s)
        gru_step<<<dim3(N3 / TN, 2), 256, SMEM_BYTES>>>(out, s);
}

// round 4
// speedup vs baseline: 1.4410x; 1.2262x over previous
#include <cuda_runtime.h>
#include <cuda_bf16.h>
#include <stdint.h>

typedef __nv_bfloat16 bf16;

#define S_LEN 512
#define BATCH 128
#define IDIM  1024
#define HDIM  1024
#define KDIM  2048       // packed weights: k<1024 -> Wih, k>=1024 -> Whh
#define N3    3072       // 3 gates * H, interleaved col = 3*j + gate
#define KT    32         // K tile
#define ASTR  40         // smem row stride (bf16): conflict-free, 16B-aligned rows
#define NSTG  3          // pipeline stages
#define MTOT  (S_LEN*BATCH)

#define TN_S  48               // step-kernel N tile (2 warp-groups x 24)
#define TN_G  96               // gi-kernel N tile   (2 warp-groups x 48)
#define NBLK_S (N3/TN_S)       // 64
#define NBLK_G (N3/TN_G)       // 32

#define STAGE_S (2*128*ASTR + 2*TN_S*ASTR)   // 14080 bf16
#define STAGE_G (2*128*ASTR + 2*TN_G*ASTR)   // 17920 bf16
#define SMEM_S  (NSTG*STAGE_S*2)             // 84480 B
#define SMEM_G  (NSTG*STAGE_G*2)             // 107520 B

// ---------------- device scratch ----------------
__device__ bf16  g_x_hi[(size_t)S_LEN*BATCH*IDIM];
__device__ bf16  g_x_lo[(size_t)S_LEN*BATCH*IDIM];
__device__ bf16  g_W_hi[(size_t)2*N3*KDIM];
__device__ bf16  g_W_lo[(size_t)2*N3*KDIM];
__device__ float g_bias[2][4][HDIM];         // br, bz, b_in, b_hn
__device__ float g_h[2*BATCH*HDIM];          // fp32 recurrent state
__device__ bf16  g_hbf_hi[2*2*BATCH*HDIM];   // [parity][dir][b][j]
__device__ bf16  g_hbf_lo[2*2*BATCH*HDIM];
__device__ float g_gi[(size_t)2*MTOT*N3];    // precomputed x@Wih^T (interleaved cols)

// ---------------- helpers ----------------
__device__ __forceinline__ void split2(float v, bf16& hi, bf16& lo) {
    hi = __float2bfloat16(v);
    lo = __float2bfloat16(v - __bfloat162float(hi));
}

__device__ __forceinline__ void cp16(bf16* dst, const bf16* src) {
    unsigned d = (unsigned)__cvta_generic_to_shared(dst);
    asm volatile("cp.async.cg.shared.global [%0], [%1], 16;\n" :: "r"(d), "l"(src));
}

__device__ __forceinline__ uint32_t smaddr(const void* p) {
    return (uint32_t)__cvta_generic_to_shared(p);
}

__device__ __forceinline__ void ldsm_x4(uint32_t r[4], uint32_t a) {
    asm volatile("ldmatrix.sync.aligned.m8n8.x4.shared.b16 {%0,%1,%2,%3},[%4];"
                 : "=r"(r[0]), "=r"(r[1]), "=r"(r[2]), "=r"(r[3]) : "r"(a));
}

__device__ __forceinline__ void mma16816(float c[4], const uint32_t a[4],
                                         uint32_t b0, uint32_t b1) {
    asm volatile(
        "mma.sync.aligned.m16n8k16.row.col.f32.bf16.bf16.f32 "
        "{%0,%1,%2,%3},{%4,%5,%6,%7},{%8,%9},{%0,%1,%2,%3};"
        : "+f"(c[0]), "+f"(c[1]), "+f"(c[2]), "+f"(c[3])
        : "r"(a[0]), "r"(a[1]), "r"(a[2]), "r"(a[3]), "r"(b0), "r"(b1));
}

__device__ __forceinline__ float fsig(float x) {
    return __fdividef(1.f, 1.f + __expf(-x));
}
__device__ __forceinline__ float ftanh(float x) {
    return 1.f - __fdividef(2.f, __expf(2.f * x) + 1.f);
}

#define CP_COMMIT() asm volatile("cp.async.commit_group;")

// ---------------- prep kernels ----------------
__global__ void pack_x_kernel(const float* __restrict__ x) {
    int i = blockIdx.x * 256 + threadIdx.x;
    bf16 hi, lo; split2(x[i], hi, lo);
    g_x_hi[i] = hi; g_x_lo[i] = lo;
}

__global__ void pack_w_kernel(const float* __restrict__ Wih_f, const float* __restrict__ Whh_f,
                              const float* __restrict__ Wih_b, const float* __restrict__ Whh_b) {
    int idx = blockIdx.x * 256 + threadIdx.x;
    int k   = idx % KDIM;
    int n   = (idx / KDIM) % N3;
    int dir = idx / (KDIM * N3);
    int j = n / 3, g = n % 3;
    int srow = g * HDIM + j;
    const float* Wih = dir ? Wih_b : Wih_f;
    const float* Whh = dir ? Whh_b : Whh_f;
    float v = (k < IDIM) ? Wih[srow * IDIM + k] : Whh[srow * HDIM + (k - IDIM)];
    bf16 hi, lo; split2(v, hi, lo);
    g_W_hi[idx] = hi; g_W_lo[idx] = lo;
}

__global__ void pack_bias_kernel(const float* __restrict__ bih_f, const float* __restrict__ bhh_f,
                                 const float* __restrict__ bih_b, const float* __restrict__ bhh_b) {
    int i = blockIdx.x * 256 + threadIdx.x;   // 0..2047
    int dir = i >> 10, j = i & 1023;
    const float* bih = dir ? bih_b : bih_f;
    const float* bhh = dir ? bhh_b : bhh_f;
    g_bias[dir][0][j] = bih[j] + bhh[j];
    g_bias[dir][1][j] = bih[HDIM + j] + bhh[HDIM + j];
    g_bias[dir][2][j] = bih[2 * HDIM + j];
    g_bias[dir][3][j] = bhh[2 * HDIM + j];
}

__global__ void init_h_kernel() {
    int i = blockIdx.x * 256 + threadIdx.x;   // 2*2*B*H
    if (i < 2 * BATCH * HDIM) g_h[i] = 0.f;
    bf16 z = __float2bfloat16(0.f);
    g_hbf_hi[i] = z; g_hbf_lo[i] = z;
}

// ---------------- mainloop compute (warp = 16 rows x NT*8 cols) ----------------
template<int NT, int BROWS>
__device__ __forceinline__ void compute_tile(bf16* stage, int mwarp, int ngrp,
                                             int lane, float acc[NT][4]) {
    bf16* pAh = stage;
    bf16* pAl = stage + 128 * ASTR;
    bf16* pBh = stage + 2 * 128 * ASTR;
    bf16* pBl = pBh + BROWS * ASTR;
    const int arow = mwarp * 16 + (lane & 15);
    const int acoff = (lane >> 4) * 8;
    const bf16* bbase = (lane < 16) ? pBh : pBl;
    const int brow0 = ngrp * (NT * 8) + (lane & 7);
    const int bcoff = ((lane >> 3) & 1) * 8;
#pragma unroll
    for (int ks = 0; ks < 2; ++ks) {
        const int kb = ks * 16;
        uint32_t ah[4], al[4];
        ldsm_x4(ah, smaddr(pAh + arow * ASTR + kb + acoff));
        ldsm_x4(al, smaddr(pAl + arow * ASTR + kb + acoff));
#pragma unroll
        for (int nt = 0; nt < NT; ++nt) {
            uint32_t b4[4];
            ldsm_x4(b4, smaddr(bbase + (brow0 + nt * 8) * ASTR + kb + bcoff));
            mma16816(acc[nt], ah, b4[0], b4[1]);   // hi*hi
            mma16816(acc[nt], ah, b4[2], b4[3]);   // hi*lo
            mma16816(acc[nt], al, b4[0], b4[1]);   // lo*hi
        }
    }
}

// ---------------- pre-GEMM: gi = x @ Wih^T for all steps ----------------
// grid: (NBLK_G=32, MTOT/128=512, 2), block 512
__global__ void __launch_bounds__(512) gi_gemm() {
    extern __shared__ char smraw[];
    bf16* sm = (bf16*)smraw;

    const int nblk = blockIdx.x, mblk = blockIdx.y, dir = blockIdx.z;
    const int t = threadIdx.x, warp = t >> 5, lane = t & 31;
    const int mwarp = warp & 7, ngrp = warp >> 3;
    const int grp = lane >> 2, tq = lane & 3;

    auto stage = [&](int s) { return sm + s * STAGE_G; };

    auto copy_tile = [&](int kt, int buf) {
        bf16* st = stage(buf);
        const int k0 = kt * KT;
        {
            int row = t >> 2;                 // 512 threads -> 128 rows x 4 quads
            int kq  = (t & 3) * 8;
            size_t off = ((size_t)mblk * 128 + row) * IDIM + k0 + kq;
            cp16(st + row * ASTR + kq, g_x_hi + off);
            cp16(st + 128 * ASTR + row * ASTR + kq, g_x_lo + off);
        }
        if (t < 4 * TN_G) {
            int nloc = t >> 2;
            int kq   = (t & 3) * 8;
            size_t off = ((size_t)(dir * N3 + nblk * TN_G + nloc)) * KDIM + k0 + kq;
            cp16(st + 2 * 128 * ASTR + nloc * ASTR + kq, g_W_hi + off);
            cp16(st + 2 * 128 * ASTR + TN_G * ASTR + nloc * ASTR + kq, g_W_lo + off);
        }
    };

    float acc[6][4];
#pragma unroll
    for (int i = 0; i < 6; i++)
#pragma unroll
        for (int q = 0; q < 4; q++) acc[i][q] = 0.f;

    copy_tile(0, 0); CP_COMMIT();
    copy_tile(1, 1); CP_COMMIT();

    const int NKT = IDIM / KT;   // 32
#pragma unroll 1
    for (int kt = 0; kt < NKT; ++kt) {
        if (kt < NKT - 1) asm volatile("cp.async.wait_group 1;");
        else              asm volatile("cp.async.wait_group 0;");
        __syncthreads();
        if (kt + 2 < NKT) { copy_tile(kt + 2, (kt + 2) % NSTG); CP_COMMIT(); }
        compute_tile<6, TN_G>(stage(kt % NSTG), mwarp, ngrp, lane, acc);
        __syncthreads();
    }

    // epilogue: write fragments straight to g_gi
    const int m = mblk * 128 + mwarp * 16 + grp;
    const int colbase = nblk * TN_G + ngrp * 48 + tq * 2;
    float* dst0 = g_gi + ((size_t)dir * MTOT + m) * N3;
    float* dst1 = dst0 + (size_t)8 * N3;
#pragma unroll
    for (int nt = 0; nt < 6; ++nt) {
        int col = colbase + nt * 8;
        dst0[col]     = acc[nt][0];
        dst0[col + 1] = acc[nt][1];
        dst1[col]     = acc[nt][2];
        dst1[col + 1] = acc[nt][3];
    }
}

// ---------------- recurrent step: gh = h @ Whh^T, then gates ----------------
// grid: (NBLK_S=64, 2), block 512
__global__ void __launch_bounds__(512) gru_step(float* __restrict__ out, int step) {
    extern __shared__ char smraw[];
    bf16* sm = (bf16*)smraw;

    const int nblk = blockIdx.x, dir = blockIdx.y;
    const int t = threadIdx.x, warp = t >> 5, lane = t & 31;
    const int mwarp = warp & 7, ngrp = warp >> 3;
    const int grp = lane >> 2, tq = lane & 3;
    const int rpar = step & 1, wpar = rpar ^ 1;
    const int s_x  = dir ? (S_LEN - 1 - step) : step;

    auto stage = [&](int s) { return sm + s * STAGE_S; };

    auto copy_tile = [&](int kt, int buf) {
        bf16* st = stage(buf);
        const int k0 = kt * KT;
        {
            int row = t >> 2;
            int kq  = (t & 3) * 8;
            int off = ((rpar * 2 + dir) * BATCH + row) * HDIM + k0 + kq;
            cp16(st + row * ASTR + kq, g_hbf_hi + off);
            cp16(st + 128 * ASTR + row * ASTR + kq, g_hbf_lo + off);
        }
        if (t < 4 * TN_S) {
            int nloc = t >> 2;
            int kq   = (t & 3) * 8;
            size_t off = ((size_t)(dir * N3 + nblk * TN_S + nloc)) * KDIM + IDIM + k0 + kq;
            cp16(st + 2 * 128 * ASTR + nloc * ASTR + kq, g_W_hi + off);
            cp16(st + 2 * 128 * ASTR + TN_S * ASTR + nloc * ASTR + kq, g_W_lo + off);
        }
    };

    float acc[3][4];
#pragma unroll
    for (int i = 0; i < 3; i++)
#pragma unroll
        for (int q = 0; q < 4; q++) acc[i][q] = 0.f;

    copy_tile(0, 0); CP_COMMIT();
    copy_tile(1, 1); CP_COMMIT();

    const int NKT = HDIM / KT;   // 32
#pragma unroll 1
    for (int kt = 0; kt < NKT; ++kt) {
        if (kt < NKT - 1) asm volatile("cp.async.wait_group 1;");
        else              asm volatile("cp.async.wait_group 0;");
        __syncthreads();
        if (kt + 2 < NKT) { copy_tile(kt + 2, (kt + 2) % NSTG); CP_COMMIT(); }
        compute_tile<3, TN_S>(stage(kt % NSTG), mwarp, ngrp, lane, acc);
        __syncthreads();
    }

    // ---- epilogue: accumulators -> smem, then GRU gates ----
    float* sC = (float*)smraw;   // [128][49]
    {
        const int row  = mwarp * 16 + grp;
        const int colb = ngrp * 24 + tq * 2;
#pragma unroll
        for (int nt = 0; nt < 3; ++nt) {
            int col = colb + nt * 8;
            sC[row * 49 + col]           = acc[nt][0];
            sC[row * 49 + col + 1]       = acc[nt][1];
            sC[(row + 8) * 49 + col]     = acc[nt][2];
            sC[(row + 8) * 49 + col + 1] = acc[nt][3];
        }
    }
    __syncthreads();

    const size_t gibase = ((size_t)dir * MTOT + (size_t)s_x * BATCH) * N3 + nblk * TN_S;
#pragma unroll
    for (int q = 0; q < 4; q++) {
        int p  = t * 4 + q;          // 2048 (b, jj) pairs
        int b  = p >> 4, jj = p & 15;
        int j  = nblk * 16 + jj;
        int c  = jj * 3;
        float ghr = sC[b * 49 + c];
        float ghz = sC[b * 49 + c + 1];
        float gnh = sC[b * 49 + c + 2] + g_bias[dir][3][j];
        const float* gip = g_gi + gibase + (size_t)b * N3 + c;
        float gr  = ghr + gip[0] + g_bias[dir][0][j];
        float gz  = ghz + gip[1] + g_bias[dir][1][j];
        float gni = gip[2] + g_bias[dir][2][j];
        float r = fsig(gr);
        float z = fsig(gz);
        float n = ftanh(gni + r * gnh);
        int   hidx = (dir * BATCH + b) * HDIM + j;
        float hold = g_h[hidx];
        float hnew = (1.f - z) * n + z * hold;
        g_h[hidx] = hnew;
        bf16 hi, lo; split2(hnew, hi, lo);
        int hb = ((wpar * 2 + dir) * BATCH + b) * HDIM + j;
        g_hbf_hi[hb] = hi;
        g_hbf_lo[hb] = lo;
        out[((size_t)step * BATCH + b) * (2 * HDIM) + dir * HDIM + j] = hnew;
    }
}

// ---------------- launch ----------------
extern "C" void kernel_launch(void* const* d_in, const int* in_sizes, int n_in,
                              void* d_out, int out_size) {
    const float* x     = (const float*)d_in[0];
    const float* Wih_f = (const float*)d_in[1];
    const float* Whh_f = (const float*)d_in[2];
    const float* bih_f = (const float*)d_in[3];
    const float* bhh_f = (const float*)d_in[4];
    const float* Wih_b = (const float*)d_in[5];
    const float* Whh_b = (const float*)d_in[6];
    const float* bih_b = (const float*)d_in[7];
    const float* bhh_b = (const float*)d_in[8];
    float* out = (float*)d_out;

    cudaFuncSetAttribute(gi_gemm,  cudaFuncAttributeMaxDynamicSharedMemorySize, SMEM_G);
    cudaFuncSetAttribute(gru_step, cudaFuncAttributeMaxDynamicSharedMemorySize, SMEM_S);

    pack_x_kernel<<<(int)((size_t)S_LEN * BATCH * IDIM / 256), 256>>>(x);
    pack_w_kernel<<<2 * N3 * KDIM / 256, 256>>>(Wih_f, Whh_f, Wih_b, Whh_b);
    pack_bias_kernel<<<8, 256>>>(bih_f, bhh_f, bih_b, bhh_b);
    init_h_kernel<<<2 * 2 * BATCH * HDIM / 256, 256>>>();

    gi_gemm<<<dim3(NBLK_G, MTOT / 128, 2), 512, SMEM_G>>>();

    for (int s = 0; s < S_LEN; ++s)
        gru_step<<<dim3(NBLK_S, 2), 512, SMEM_S>>>(out, s);
}